// round 5
// baseline (speedup 1.0000x reference)
#include <cuda_runtime.h>

// KVCacheHeadAttention: B=32, E=4096 -> D=128, MAX_TOKENS=2048.
// Prefix-softmax: out[b,s,:] = sum_{t<=s} e_t*v[b,t,:] / sum_{t<=s} e_t.
// R4: single-pass fused score+scan kernel with decoupled lookback
// (publish chunk totals -> fence -> flag; successors spin, sum, scan).
// Removes the duplicate V pass, the g_e round-trip, and one kernel launch.

#define BB 32
#define DD 128
#define D4 32
#define EE 4096
#define MAXT 2048
#define CHUNK 128
#define MAXCH 16

__device__ float g_qkv[3][BB][DD];
__device__ float g_ctot[BB][MAXCH][DD];   // chunk numerator totals
__device__ float g_dtot[BB][MAXCH];       // chunk denominator totals
__device__ int   g_flag[BB][MAXCH];       // publish flags

__device__ __forceinline__ float4 f4add(float4 a, float4 b) {
    return make_float4(a.x+b.x, a.y+b.y, a.z+b.z, a.w+b.w);
}
__device__ __forceinline__ float4 f4fma(float s, float4 v, float4 a) {
    return make_float4(fmaf(s,v.x,a.x), fmaf(s,v.y,a.y),
                       fmaf(s,v.z,a.z), fmaf(s,v.w,a.w));
}
__device__ __forceinline__ float4 f4scale(float4 v, float s) {
    return make_float4(v.x*s, v.y*s, v.z*s, v.w*s);
}

// ---------------------------------------------------- K0: zero qkv + flags
__global__ void zero_kernel() {
    int i = blockIdx.x * 256 + threadIdx.x;
    if (i < 3 * BB * DD) ((float*)g_qkv)[i] = 0.0f;
    if (i < BB * MAXCH) ((int*)g_flag)[i] = 0;
}

// ------------------------------------------------- K1: QKV split-K GEMM
#define ECH 128
__global__ __launch_bounds__(256) void qkv_kernel(
    const float* __restrict__ x, const float* __restrict__ Wq,
    const float* __restrict__ Wk, const float* __restrict__ Wv) {
    __shared__ float xs[32][ECH + 4];
    __shared__ float ws[32][ECH + 4];
    int m  = blockIdx.x >> 2;
    int dt = blockIdx.x & 3;
    const float* W = (m == 0) ? Wq : ((m == 1) ? Wk : Wv);
    int e0  = blockIdx.y * ECH;
    int tid = threadIdx.x;

    for (int i = tid; i < 32 * (ECH / 4); i += 256) {
        int r = i >> 5;
        int j = (i & 31) << 2;
        *(float4*)&xs[r][j] = *(const float4*)(x + (size_t)r * EE + e0 + j);
        *(float4*)&ws[r][j] = *(const float4*)(W + (size_t)(dt * 32 + r) * EE + e0 + j);
    }
    __syncthreads();

    int ti = tid & 15, tj = tid >> 4;
    float a00 = 0.f, a01 = 0.f, a10 = 0.f, a11 = 0.f;
    #pragma unroll
    for (int e = 0; e < ECH; e += 4) {
        float4 xa = *(float4*)&xs[ti][e];
        float4 xb = *(float4*)&xs[ti + 16][e];
        float4 wa = *(float4*)&ws[tj][e];
        float4 wb = *(float4*)&ws[tj + 16][e];
        a00 += xa.x*wa.x + xa.y*wa.y + xa.z*wa.z + xa.w*wa.w;
        a01 += xa.x*wb.x + xa.y*wb.y + xa.z*wb.z + xa.w*wb.w;
        a10 += xb.x*wa.x + xb.y*wa.y + xb.z*wa.z + xb.w*wa.w;
        a11 += xb.x*wb.x + xb.y*wb.y + xb.z*wb.z + xb.w*wb.w;
    }
    atomicAdd(&g_qkv[m][ti][dt * 32 + tj],           a00);
    atomicAdd(&g_qkv[m][ti][dt * 32 + tj + 16],      a01);
    atomicAdd(&g_qkv[m][ti + 16][dt * 32 + tj],      a10);
    atomicAdd(&g_qkv[m][ti + 16][dt * 32 + tj + 16], a11);
}

// --------------- K2: fused score + chunk totals + lookback + scan
// grid(nchunks, B), 512 threads. Block = 128-token chunk of one batch.
__global__ __launch_bounds__(512) void fused_kernel(
    const float* __restrict__ kv, const int* __restrict__ np,
    float* __restrict__ out, int max_k) {
    int b = blockIdx.y, c = blockIdx.x, tid = threadIdx.x;
    __shared__ float qs[DD], kn[DD], es[CHUNK], rden[CHUNK];
    __shared__ float4 vns4[D4];
    __shared__ float4 part[16][D4];     // 8-token partials, reused for lookback
    __shared__ float pden[16];          // lookback den slots
    __shared__ float warp_sums[4];

    if (tid < DD) {
        qs[tid] = g_qkv[0][b][tid];
        kn[tid] = g_qkv[1][b][tid];
        if ((tid & 3) == 0)
            vns4[tid >> 2] = *(const float4*)&g_qkv[2][b][tid];
    }
    __syncthreads();

    int npos = np[b];
    int t0   = c * CHUNK;

    // --- phase 1: scores. token = tid>>2, quarter-dot per lane.
    {
        int tok = tid >> 2, qq = tid & 3;
        int t   = t0 + tok;
        const float* krow = (t == npos) ? kn
                          : kv + ((size_t)b * MAXT + t) * DD;
        float s = 0.0f;
        int d0 = qq * 32;
        #pragma unroll
        for (int d = 0; d < 32; d += 4) {
            float4 kk = *(const float4*)(krow + d0 + d);
            s += qs[d0+d]*kk.x + qs[d0+d+1]*kk.y + qs[d0+d+2]*kk.z + qs[d0+d+3]*kk.w;
        }
        s += __shfl_xor_sync(0xffffffffu, s, 1);
        s += __shfl_xor_sync(0xffffffffu, s, 2);
        float e = (t < max_k) ? expf(s * 0.08838834764831845f) : 0.0f;
        if (qq == 0) es[tok] = e;
    }
    __syncthreads();

    // --- phase 2: 8-token numerator partials; den warp-scan.
    int s  = tid >> 5;       // 0..15  (one warp per 8-token sub-chunk)
    int d4 = tid & 31;
    int tb = t0 + s * 8;
    const float4* vbase = (const float4*)(kv + (size_t)BB * MAXT * DD
                                          + ((size_t)b * MAXT + tb) * DD) + d4;
    {
        float4 psum = make_float4(0.f, 0.f, 0.f, 0.f);
        #pragma unroll
        for (int u = 0; u < 8; u++) {
            float4 x = vbase[(size_t)u * D4];        // in-bounds (< MAXT)
            if (tb + u == npos) x = vns4[d4];
            psum = f4fma(es[s * 8 + u], x, psum);
        }
        part[s][d4] = psum;
    }
    // den inclusive warp-scan over the 128 es (warps 0..3)
    float dv = 0.0f;
    if (tid < 128) {
        dv = es[tid];
        int lane = tid & 31;
        #pragma unroll
        for (int o = 1; o < 32; o <<= 1) {
            float n = __shfl_up_sync(0xffffffffu, dv, o);
            if (lane >= o) dv += n;
        }
        if (lane == 31) warp_sums[tid >> 5] = dv;
    }
    __syncthreads();

    // --- exclusive prefix over own 8-token partials (register), publish total
    float4 pref = make_float4(0.f, 0.f, 0.f, 0.f);
    for (int j = 0; j < s; j++) pref = f4add(pref, part[j][d4]);
    if (s == 15)
        *((float4*)&g_ctot[b][c][0] + d4) = f4add(pref, part[15][d4]);
    if (tid == 0)
        g_dtot[b][c] = warp_sums[0] + warp_sums[1] + warp_sums[2] + warp_sums[3];
    __syncthreads();
    if (tid == 0) {
        __threadfence();
        atomicExch(&g_flag[b][c], 1);
    }

    // --- lookback: warp i (i < c) fetches predecessor i's totals
    if (s < c) {
        volatile int* fl = &g_flag[b][s];
        while (*fl == 0) { __nanosleep(64); }
        __threadfence();
        part[s][d4] = *((const float4*)&g_ctot[b][s][0] + d4);
        if (d4 == 0) pden[s] = g_dtot[b][s];
    } else {
        part[s][d4] = make_float4(0.f, 0.f, 0.f, 0.f);
        if (d4 == 0) pden[s] = 0.0f;
    }
    __syncthreads();

    // --- bases + reciprocal denominators
    float4 bnum = make_float4(0.f, 0.f, 0.f, 0.f);
    float  bden = 0.0f;
    for (int i = 0; i < c; i++) {
        bnum = f4add(bnum, part[i][d4]);
        bden += pden[i];
    }
    if (tid < 128) {
        int w = tid >> 5;
        float wb = bden;
        for (int i = 0; i < w; i++) wb += warp_sums[i];
        rden[tid] = 1.0f / (wb + dv);
    }
    __syncthreads();

    // --- final scan: reload V (L2-hot), fma, scaled store
    float4 acc = f4add(bnum, pref);
    float4* obase = (float4*)(out + ((size_t)b * max_k + tb) * DD) + d4;
    #pragma unroll
    for (int u = 0; u < 8; u++) {
        float4 x = vbase[(size_t)u * D4];
        if (tb + u == npos) x = vns4[d4];
        acc = f4fma(es[s * 8 + u], x, acc);
        if (tb + u < max_k)
            obase[(size_t)u * D4] = f4scale(acc, rden[s * 8 + u]);
    }
}

// ----------------------------------------------------------------- launch
extern "C" void kernel_launch(void* const* d_in, const int* in_sizes, int n_in,
                              void* d_out, int out_size) {
    const float* x   = (const float*)d_in[0];
    const float* Wq  = (const float*)d_in[1];
    const float* Wk  = (const float*)d_in[2];
    const float* Wv  = (const float*)d_in[3];
    const float* kvc = (const float*)d_in[4];
    const int*   np  = (const int*)d_in[5];
    float* out = (float*)d_out;

    int max_k   = out_size / (BB * DD);
    int nchunks = (max_k + CHUNK - 1) / CHUNK;   // <= MAXCH

    zero_kernel<<<48, 256>>>();
    qkv_kernel<<<dim3(12, 32), 256>>>(x, Wq, Wk, Wv);
    fused_kernel<<<dim3(nchunks, BB), 512>>>(kvc, np, out, max_k);
}